// round 14
// baseline (speedup 1.0000x reference)
#include <cuda_runtime.h>
#include <cuda_bf16.h>
#include <math.h>
#include <stdint.h>

#define NSC 128
#define NVC 64
#define TPCC 192
#define NNODES 16000
#define NEDGES 256000
#define NTILES 2000           // NEDGES / 128

#define INV_SQRT_NS 0.08838834764831845f
#define INV_SQRT_NV 0.125f
#define INV_SQRT_TPC 0.07216878364870323f
#define INV_SQRT3 0.5773502691896258f

// ---------------- scratch (static device globals; no runtime allocs) --------
__device__ float g_xs[NNODES * NSC];            // [n][128]
__device__ float g_xv[NNODES * 3 * NVC];        // [n][c][64]
__device__ float g_accs[NNODES * TPCC];         // [n][192]
__device__ float g_accv[NNODES * 3 * TPCC];     // [n][c][192]
// h split into bf16 hi/lo, row-major [e][128]
__device__ __nv_bfloat16 g_hhi[(size_t)NEDGES * 128];
__device__ __nv_bfloat16 g_hlo[(size_t)NEDGES * 128];
// W2 packed into mma.sync B fragments, PERMUTED stage-major
__device__ uint4 g_Bpk[6 * 8 * 8 * 32];
// transposed post weights: [j][u] row-contiguous
__device__ float g_WpsT[128 * 192];
__device__ float g_WpvT[64 * 192];

// stage column permutation: stage cs, within-stage col sc (0..63) -> W2 col.
__host__ __device__ __forceinline__ int perm_col(int cs, int sc) {
    if (cs < 4)
        return (sc < 32) ? (cs * 32 + sc) : (192 + cs * 32 + (sc - 32));
    else
        return (sc < 32) ? (128 + (cs - 4) * 32 + sc)
                         : (320 + (cs - 4) * 32 + (sc - 32));
}

// ---------------- generic helpers -------------------------------------------
__device__ __forceinline__ float silu_f(float x) {
    return x / (1.0f + __expf(-x));
}
__device__ __forceinline__ float4 f4mul(float4 a, float4 b) {
    return make_float4(a.x * b.x, a.y * b.y, a.z * b.z, a.w * b.w);
}
__device__ __forceinline__ float4 f4scale(float4 a, float s) {
    return make_float4(a.x * s, a.y * s, a.z * s, a.w * s);
}
__device__ __forceinline__ float4 f4fmas(float4 a, float s, float4 c) {
    return make_float4(fmaf(a.x, s, c.x), fmaf(a.y, s, c.y),
                       fmaf(a.z, s, c.z), fmaf(a.w, s, c.w));
}
__device__ __forceinline__ void red4(float* p, float4 v) {
    asm volatile("red.global.add.v4.f32 [%0], {%1, %2, %3, %4};"
                 :: "l"(p), "f"(v.x), "f"(v.y), "f"(v.z), "f"(v.w)
                 : "memory");
}
__device__ __forceinline__ unsigned short bf_bits(__nv_bfloat16 h) {
    return *(unsigned short*)&h;
}
__device__ __forceinline__ void bf_split(float x, unsigned short& hi,
                                         unsigned short& lo) {
    const __nv_bfloat16 h = __float2bfloat16(x);
    const __nv_bfloat16 l = __float2bfloat16(x - __bfloat162float(h));
    hi = bf_bits(h);
    lo = bf_bits(l);
}

// mma.sync m16n8k16 bf16, fp32 accum
__device__ __forceinline__ void mma_bf16(float c[4], const uint4& a,
                                         uint32_t b0, uint32_t b1) {
    asm volatile(
        "mma.sync.aligned.m16n8k16.row.col.f32.bf16.bf16.f32 "
        "{%0,%1,%2,%3}, {%4,%5,%6,%7}, {%8,%9}, {%0,%1,%2,%3};"
        : "+f"(c[0]), "+f"(c[1]), "+f"(c[2]), "+f"(c[3])
        : "r"(a.x), "r"(a.y), "r"(a.z), "r"(a.w), "r"(b0), "r"(b1));
}

// cp.async + mbarrier helpers
__device__ __forceinline__ void cp16(void* dst_smem, const void* src) {
    uint32_t d = (uint32_t)__cvta_generic_to_shared(dst_smem);
    asm volatile("cp.async.cg.shared.global [%0], [%1], 16;"
                 :: "r"(d), "l"(src) : "memory");
}
#define MBAR_INIT(mb, n) \
    asm volatile("mbarrier.init.shared.b64 [%0], %1;" \
                 :: "r"(mb), "r"((uint32_t)(n)) : "memory")
#define MBAR_ARRIVE(mb) \
    asm volatile("mbarrier.arrive.shared.b64 _, [%0];" :: "r"(mb) : "memory")
#define CP_MBAR_ARRIVE(mb) \
    asm volatile("cp.async.mbarrier.arrive.noinc.shared.b64 [%0];" \
                 :: "r"(mb) : "memory")
#define MBAR_TRYWAIT(mb, par) do { \
    asm volatile( \
        "{\n\t.reg .pred P1;\n\t" \
        "WL_%=:\n\t" \
        "mbarrier.try_wait.parity.shared.b64 P1, [%0], %1;\n\t" \
        "@P1 bra.uni WD_%=;\n\t" \
        "bra.uni WL_%=;\n\t" \
        "WD_%=:\n\t}" \
        :: "r"(mb), "r"((uint32_t)(par)) : "memory"); \
} while (0)

// ---------------- K1: node pre-mix ------------------------------------------
__global__ __launch_bounds__(320) void k_node_pre(
    const float* __restrict__ nf, const float* __restrict__ Ws,
    const float* __restrict__ bs, const float* __restrict__ Wv)
{
    __shared__ float sv[8][320];
    const int n0 = blockIdx.x * 8;
    const int tid = threadIdx.x;

    for (int idx = tid; idx < 8 * 320; idx += 320) {
        sv[idx / 320][idx % 320] = nf[(n0 + idx / 320) * 320 + idx % 320];
    }
    __syncthreads();

    if (tid < 128) {
        const int j = tid;
        float acc[8];
#pragma unroll
        for (int i = 0; i < 8; i++) acc[i] = 0.0f;
        for (int u = 0; u < 128; u++) {
            const float w = Ws[u * 128 + j];
#pragma unroll
            for (int i = 0; i < 8; i++) acc[i] = fmaf(sv[i][u], w, acc[i]);
        }
        const float b = bs[j];
#pragma unroll
        for (int i = 0; i < 8; i++)
            g_xs[(n0 + i) * 128 + j] = fmaf(acc[i], INV_SQRT_NS, b);
    } else {
        const int t = tid - 128;
        const int c = t / 64, vp = t % 64;
        float acc[8];
#pragma unroll
        for (int i = 0; i < 8; i++) acc[i] = 0.0f;
        for (int u = 0; u < 64; u++) {
            const float w = Wv[u * 64 + vp];
#pragma unroll
            for (int i = 0; i < 8; i++)
                acc[i] = fmaf(sv[i][128 + 3 * u + c], w, acc[i]);
        }
#pragma unroll
        for (int i = 0; i < 8; i++)
            g_xv[(n0 + i) * 192 + c * 64 + vp] = acc[i] * INV_SQRT_NV;
    }
}

// ---------------- prep: W2 -> packed, PERMUTED B fragments -------------------
__global__ __launch_bounds__(256) void k_prep_b(const float* __restrict__ W2)
{
    const int idx = blockIdx.x * 256 + threadIdx.x;
    if (idx >= 6 * 8 * 8 * 32) return;
    const int lane = idx & 31;
    const int jj = (idx >> 5) & 7;
    const int s = (idx >> 8) & 7;
    const int cs = idx >> 11;

    const int gid = lane >> 2;
    const int tig = lane & 3;
    const int wcol = perm_col(cs, jj * 8 + gid);
    const int k0 = s * 16 + tig * 2;

    unsigned short h0, l0, h1, l1, h2, l2, h3, l3;
    bf_split(W2[k0 * 384 + wcol],       h0, l0);
    bf_split(W2[(k0 + 1) * 384 + wcol], h1, l1);
    bf_split(W2[(k0 + 8) * 384 + wcol], h2, l2);
    bf_split(W2[(k0 + 9) * 384 + wcol], h3, l3);

    uint4 p;
    p.x = (uint32_t)h0 | ((uint32_t)h1 << 16);
    p.y = (uint32_t)h2 | ((uint32_t)h3 << 16);
    p.z = (uint32_t)l0 | ((uint32_t)l1 << 16);
    p.w = (uint32_t)l2 | ((uint32_t)l3 << 16);
    g_Bpk[((cs * 8 + s) * 8 + jj) * 32 + lane] = p;
}

// ---------------- prep: transpose post weights -------------------------------
__global__ __launch_bounds__(256) void k_prep_post(
    const float* __restrict__ Wps, const float* __restrict__ Wpv)
{
    const int idx = blockIdx.x * 256 + threadIdx.x;
    if (idx < 192 * 128) {
        const int u = idx / 128, j = idx % 128;
        g_WpsT[j * 192 + u] = Wps[u * 128 + j];
    }
    if (idx < 192 * 64) {
        const int u = idx / 64, v = idx % 64;
        g_WpvT[v * 192 + u] = Wpv[u * 64 + v];
    }
}

// ---------------- K2: edge MLP layer 1 -> h hi/lo bf16 -----------------------
__global__ __launch_bounds__(256) void k_edge_mlp1(
    const float* __restrict__ ea, const float* __restrict__ W1,
    const float* __restrict__ b1)
{
    __shared__ float W1s[16 * 128];
    __shared__ float b1s[128];
    __shared__ float eas[8][16];
    const int tid = threadIdx.x;
    const int e0 = blockIdx.x * 8;

    for (int idx = tid; idx < 2048; idx += 256) W1s[idx] = W1[idx];
    if (tid < 128) {
        b1s[tid] = b1[tid];
        eas[tid / 16][tid % 16] = ea[e0 * 16 + tid];
    }
    __syncthreads();

    const int i = tid >> 5;
    const int q = (tid & 31) * 4;
    float4 acc = *(const float4*)(b1s + q);
#pragma unroll
    for (int k = 0; k < 16; k++) {
        const float a = eas[i][k];
        const float4 w = *(const float4*)(W1s + k * 128 + q);
        acc = f4fmas(w, a, acc);
    }
    float v[4];
    v[0] = silu_f(acc.x); v[1] = silu_f(acc.y);
    v[2] = silu_f(acc.z); v[3] = silu_f(acc.w);

    unsigned short hb[4], lb[4];
#pragma unroll
    for (int j = 0; j < 4; j++) bf_split(v[j], hb[j], lb[j]);

    const size_t base = (size_t)(e0 + i) * 128 + q;
    uint2 ph, pl;
    ph.x = (uint32_t)hb[0] | ((uint32_t)hb[1] << 16);
    ph.y = (uint32_t)hb[2] | ((uint32_t)hb[3] << 16);
    pl.x = (uint32_t)lb[0] | ((uint32_t)lb[1] << 16);
    pl.y = (uint32_t)lb[2] | ((uint32_t)lb[3] << 16);
    *(uint2*)(g_hhi + base) = ph;
    *(uint2*)(g_hlo + base) = pl;
}

// ---------------- K3: FUSED tensor GEMM + interleaved scatter ----------------
#define SA_STRIDE 136
#define SMEM_A_IMG (128 * SA_STRIDE * 2)            // 34816 per image
#define SMEM_B_BYTES 32768
#define SMEM_WS_OFF (2 * SMEM_A_IMG)                // 69632
#define WS_STRIDE 68
#define SMEM_BIAS_OFF (SMEM_WS_OFF + 128 * WS_STRIDE * 4)   // 104448
#define SMEM_EIDX_OFF (SMEM_BIAS_OFF + 1536)        // 105984
#define SMEM_R_OFF    (SMEM_EIDX_OFF + 1024)        // 107008
#define SMEM_MB_OFF   (SMEM_R_OFF + 2048)           // 109056
#define SMEM_MMA_BYTES (SMEM_MB_OFF + 64)           // 109120
__global__ __launch_bounds__(256, 2) void k_mlp2_fused(
    const float* __restrict__ b2,
    const int* __restrict__ eidx, const float* __restrict__ rsh)
{
    extern __shared__ unsigned char smem[];
    __nv_bfloat16* sAh = (__nv_bfloat16*)smem;
    __nv_bfloat16* sAl = (__nv_bfloat16*)(smem + SMEM_A_IMG);
    float* ws = (float*)(smem + SMEM_WS_OFF);
    float* sbias = (float*)(smem + SMEM_BIAS_OFF);
    int* sDst = (int*)(smem + SMEM_EIDX_OFF);
    int* sSrc = sDst + 128;
    float4* sR4 = (float4*)(smem + SMEM_R_OFF);
    const uint32_t mbF =
        (uint32_t)__cvta_generic_to_shared(smem + SMEM_MB_OFF);
    const uint32_t mbE = mbF + 16;

    const int tid = threadIdx.x;
    const int warp = tid >> 5;
    const int lane = tid & 31;
    const int tile = blockIdx.x;
    const int gid = lane >> 2;
    const int tig = lane & 3;
    const int row0 = warp * 16 + gid;

    // scatter lane mapping
    const int half16 = lane >> 4;
    const int sub = lane & 15;
    const int typ = sub >> 3;
    const int l4 = (sub & 7) * 4;

    // one scatter iteration of stage sc (it = 0..7)
    auto scatter_iter = [&](int sc, int it) {
        const int t = warp * 16 + it * 2 + half16;
        const int dst = sDst[t];
        const int src = sSrc[t];
        const float4 r = sR4[t];
        const float4 w = *(const float4*)&ws[t * WS_STRIDE + typ * 32 + l4];
        float* as_ = g_accs + dst * 192;
        float* av = g_accv + dst * 576;
        if (sc < 4) {
            const int scol = sc * 32 + l4;
            const float4 sj = *(const float4*)(g_xs + src * 128 + scol);
            if (typ == 0) {
                red4(as_ + scol, f4scale(f4mul(w, sj), r.x));
            } else {
                const float4 base = f4mul(w, sj);
                red4(av + scol,       f4scale(base, r.y));
                red4(av + 192 + scol, f4scale(base, r.z));
                red4(av + 384 + scol, f4scale(base, r.w));
            }
        } else {
            const int u = (sc - 4) * 32 + l4;
            const float* xv = g_xv + src * 192;
            const float4 v0 = *(const float4*)(xv + u);
            const float4 v1 = *(const float4*)(xv + 64 + u);
            const float4 v2 = *(const float4*)(xv + 128 + u);
            if (typ == 0) {
                float4 vd = f4scale(v0, r.y);
                vd = f4fmas(v1, r.z, vd);
                vd = f4fmas(v2, r.w, vd);
                red4(as_ + 128 + u, f4scale(f4mul(w, vd), INV_SQRT3));
            } else {
                const float4 wr = f4scale(w, r.x);
                red4(av + 128 + u, f4mul(wr, v0));
                red4(av + 320 + u, f4mul(wr, v1));
                red4(av + 512 + u, f4mul(wr, v2));
            }
        }
    };

    // ---- stage A once; bias (permuted), edge meta; init mbarriers ----
    {
        const uint2* ghh = (const uint2*)(g_hhi + (size_t)tile * 16384);
        const uint2* ghl = (const uint2*)(g_hlo + (size_t)tile * 16384);
        for (int i = tid; i < 4096; i += 256) {
            const int r = i >> 5, q = (i & 31) * 4;
            *(uint2*)&sAh[r * SA_STRIDE + q] = ghh[i];
            *(uint2*)&sAl[r * SA_STRIDE + q] = ghl[i];
        }
    }
    for (int i = tid; i < 384; i += 256)
        sbias[i] = b2[perm_col(i / 64, i % 64)];
    if (tid < 128) {
        sDst[tid] = eidx[tile * 128 + tid];
        sSrc[tid] = eidx[NEDGES + tile * 128 + tid];
        sR4[tid] = *(const float4*)(rsh + 4 * (tile * 128 + tid));
    }
    if (tid == 0) {
        MBAR_INIT(mbF + 0, 256);
        MBAR_INIT(mbF + 8, 256);
        MBAR_INIT(mbE + 0, 256);
        MBAR_INIT(mbE + 8, 256);
    }
    __syncthreads();

    uint4 ah[8], al[8];
#pragma unroll
    for (int s = 0; s < 8; s++) {
        const int kb = s * 16 + tig * 2;
        ah[s].x = *(const uint32_t*)&sAh[row0 * SA_STRIDE + kb];
        ah[s].y = *(const uint32_t*)&sAh[(row0 + 8) * SA_STRIDE + kb];
        ah[s].z = *(const uint32_t*)&sAh[row0 * SA_STRIDE + kb + 8];
        ah[s].w = *(const uint32_t*)&sAh[(row0 + 8) * SA_STRIDE + kb + 8];
        al[s].x = *(const uint32_t*)&sAl[row0 * SA_STRIDE + kb];
        al[s].y = *(const uint32_t*)&sAl[(row0 + 8) * SA_STRIDE + kb];
        al[s].z = *(const uint32_t*)&sAl[row0 * SA_STRIDE + kb + 8];
        al[s].w = *(const uint32_t*)&sAl[(row0 + 8) * SA_STRIDE + kb + 8];
    }
    __syncthreads();     // A region released -> reused as B double buffer

    // prefetch stage 0 into buf0
    {
        const uint4* srcp = g_Bpk;
        uint4* dstp = (uint4*)smem;
#pragma unroll
        for (int i = 0; i < 8; i++)
            cp16(&dstp[tid + i * 256], &srcp[tid + i * 256]);
        CP_MBAR_ARRIVE(mbF + 0);
    }

    for (int cs = 0; cs < 6; cs++) {
        if (cs < 5) {
            const int b = (cs + 1) & 1;
            if (cs >= 1) MBAR_TRYWAIT(mbE + b * 8, ((cs - 1) >> 1) & 1);
            const uint4* srcp = g_Bpk + (cs + 1) * 2048;
            uint4* dstp = (uint4*)(smem + b * SMEM_B_BYTES);
#pragma unroll
            for (int i = 0; i < 8; i++)
                cp16(&dstp[tid + i * 256], &srcp[tid + i * 256]);
            CP_MBAR_ARRIVE(mbF + b * 8);
        }
        const int bc = cs & 1;
        MBAR_TRYWAIT(mbF + bc * 8, (cs >> 1) & 1);
        const uint4* bb = (const uint4*)(smem + bc * SMEM_B_BYTES);

        float c[8][4];
#pragma unroll
        for (int j = 0; j < 8; j++)
#pragma unroll
            for (int q = 0; q < 4; q++) c[j][q] = 0.0f;

        // MMA with previous stage's scatter interleaved per k-step
#pragma unroll
        for (int s = 0; s < 8; s++) {
#pragma unroll
            for (int j = 0; j < 8; j++) {
                const uint4 b = bb[(s * 8 + j) * 32 + lane];
                mma_bf16(c[j], ah[s], b.x, b.y);
                mma_bf16(c[j], ah[s], b.z, b.w);
                mma_bf16(c[j], al[s], b.x, b.y);
            }
            if (cs > 0) scatter_iter(cs - 1, s);
        }
        MBAR_ARRIVE(mbE + bc * 8);   // done reading this B buffer

        // ---- stage w to warp-local ws rows (bias added) ----
        const int cbase = cs * 64;
#pragma unroll
        for (int j = 0; j < 8; j++) {
            const int cl = j * 8 + tig * 2;
            const float bx = sbias[cbase + cl], by = sbias[cbase + cl + 1];
            *(float2*)&ws[row0 * WS_STRIDE + cl] =
                make_float2(c[j][0] + bx, c[j][1] + by);
            *(float2*)&ws[(row0 + 8) * WS_STRIDE + cl] =
                make_float2(c[j][2] + bx, c[j][3] + by);
        }
        __syncwarp();
    }

    // tail: scatter of stage 5
#pragma unroll
    for (int it = 0; it < 8; it++) scatter_iter(5, it);
}

// ---------------- K5: gating + node post-mix (transposed W) ------------------
__global__ __launch_bounds__(320) void k_node_post(
    float* __restrict__ out)
{
    __shared__ float gs[8][192];
    __shared__ float gv[8][3][192];
    const int n0 = blockIdx.x * 8;
    const int tid = threadIdx.x;

    for (int idx = tid; idx < 8 * 192; idx += 320) {
        const int i = idx / 192, u = idx % 192;
        const float a = g_accs[(n0 + i) * 192 + u];
        gs[i][u] = silu_f(a);
        const float v0 = g_accv[(n0 + i) * 576 + u];
        const float v1 = g_accv[(n0 + i) * 576 + 192 + u];
        const float v2 = g_accv[(n0 + i) * 576 + 384 + u];
        const float nrm = sqrtf(fmaf(v0, v0, fmaf(v1, v1, fmaf(v2, v2, 1e-12f))));
        const float sg = 1.0f / (1.0f + __expf(-nrm));
        gv[i][0][u] = v0 * sg;
        gv[i][1][u] = v1 * sg;
        gv[i][2][u] = v2 * sg;
    }
    __syncthreads();

    if (tid < 128) {
        const int j = tid;
        const float4* wrow = (const float4*)(g_WpsT + j * 192);
        float acc[8];
#pragma unroll
        for (int i = 0; i < 8; i++) acc[i] = 0.0f;
        for (int u = 0; u < 192; u += 4) {
            const float4 w = wrow[u >> 2];
#pragma unroll
            for (int i = 0; i < 8; i++) {
                const float4 g = *(const float4*)&gs[i][u];
                acc[i] = fmaf(g.x, w.x, acc[i]);
                acc[i] = fmaf(g.y, w.y, acc[i]);
                acc[i] = fmaf(g.z, w.z, acc[i]);
                acc[i] = fmaf(g.w, w.w, acc[i]);
            }
        }
#pragma unroll
        for (int i = 0; i < 8; i++)
            out[(n0 + i) * 320 + j] =
                g_xs[(n0 + i) * 128 + j] + acc[i] * INV_SQRT_TPC;
    } else {
        const int t = tid - 128;
        const int c = t / 64, vp = t % 64;
        const float4* wrow = (const float4*)(g_WpvT + vp * 192);
        float acc[8];
#pragma unroll
        for (int i = 0; i < 8; i++) acc[i] = 0.0f;
        for (int u = 0; u < 192; u += 4) {
            const float4 w = wrow[u >> 2];
#pragma unroll
            for (int i = 0; i < 8; i++) {
                const float4 g = *(const float4*)&gv[i][c][u];
                acc[i] = fmaf(g.x, w.x, acc[i]);
                acc[i] = fmaf(g.y, w.y, acc[i]);
                acc[i] = fmaf(g.z, w.z, acc[i]);
                acc[i] = fmaf(g.w, w.w, acc[i]);
            }
        }
#pragma unroll
        for (int i = 0; i < 8; i++)
            out[(n0 + i) * 320 + 128 + vp * 3 + c] =
                g_xv[(n0 + i) * 192 + c * 64 + vp] + acc[i] * INV_SQRT_TPC;
    }
}

// ---------------- launcher ---------------------------------------------------
extern "C" void kernel_launch(void* const* d_in, const int* in_sizes, int n_in,
                              void* d_out, int out_size)
{
    (void)in_sizes; (void)n_in; (void)out_size;
    const float* nf   = (const float*)d_in[0];
    const float* ea   = (const float*)d_in[1];
    const float* rsh  = (const float*)d_in[2];
    const int*   eidx = (const int*)d_in[3];
    const float* Wps  = (const float*)d_in[4];
    const float* bps  = (const float*)d_in[5];
    const float* Wpv  = (const float*)d_in[6];
    const float* W1   = (const float*)d_in[7];
    const float* b1   = (const float*)d_in[8];
    const float* W2   = (const float*)d_in[9];
    const float* b2   = (const float*)d_in[10];
    const float* Wposts = (const float*)d_in[11];
    const float* Wpostv = (const float*)d_in[12];
    float* out = (float*)d_out;

    cudaFuncSetAttribute(k_mlp2_fused,
                         cudaFuncAttributeMaxDynamicSharedMemorySize,
                         SMEM_MMA_BYTES);

    void* accs_ptr = nullptr;
    void* accv_ptr = nullptr;
    cudaGetSymbolAddress(&accs_ptr, g_accs);
    cudaGetSymbolAddress(&accv_ptr, g_accv);
    cudaMemsetAsync(accs_ptr, 0, sizeof(float) * NNODES * TPCC);
    cudaMemsetAsync(accv_ptr, 0, sizeof(float) * NNODES * 3 * TPCC);

    k_node_pre<<<NNODES / 8, 320>>>(nf, Wps, bps, Wpv);
    k_prep_b<<<48, 256>>>(W2);
    k_prep_post<<<96, 256>>>(Wposts, Wpostv);
    k_edge_mlp1<<<NEDGES / 8, 256>>>(ea, W1, b1);
    k_mlp2_fused<<<NTILES, 256, SMEM_MMA_BYTES>>>(b2, eidx, rsh);
    k_node_post<<<NNODES / 8, 320>>>(out);
}

// round 15
// speedup vs baseline: 1.0336x; 1.0336x over previous
#include <cuda_runtime.h>
#include <cuda_bf16.h>
#include <math.h>
#include <stdint.h>

#define NSC 128
#define NVC 64
#define TPCC 192
#define NNODES 16000
#define NEDGES 256000
#define NTILES 2000           // NEDGES / 128

#define INV_SQRT_NS 0.08838834764831845f
#define INV_SQRT_NV 0.125f
#define INV_SQRT_TPC 0.07216878364870323f
#define INV_SQRT3 0.5773502691896258f

// ---------------- scratch (static device globals; no runtime allocs) --------
__device__ float g_xs[NNODES * NSC];            // [n][128]
__device__ float g_xv[NNODES * 3 * NVC];        // [n][c][64]
__device__ float g_accs[NNODES * TPCC];         // [n][192]
__device__ float g_accv[NNODES * 3 * TPCC];     // [n][c][192]
// h split into bf16 hi/lo, row-major [e][128]
__device__ __nv_bfloat16 g_hhi[(size_t)NEDGES * 128];
__device__ __nv_bfloat16 g_hlo[(size_t)NEDGES * 128];
// W2 packed into mma.sync B fragments, PERMUTED stage-major
__device__ uint4 g_Bpk[6 * 8 * 8 * 32];
// transposed post weights: [j][u] row-contiguous
__device__ float g_WpsT[128 * 192];
__device__ float g_WpvT[64 * 192];

// stage column permutation: stage cs, within-stage col sc (0..63) -> W2 col.
// S0-3: [ w_ss0[cs*32 : +32] | w_sv1[cs*32 : +32] ]   (share xs gather)
// S4-5: [ w_vv0[(cs-4)*32:+32] | w_vs1[(cs-4)*32:+32] ] (share xv gather)
__host__ __device__ __forceinline__ int perm_col(int cs, int sc) {
    if (cs < 4)
        return (sc < 32) ? (cs * 32 + sc) : (192 + cs * 32 + (sc - 32));
    else
        return (sc < 32) ? (128 + (cs - 4) * 32 + sc)
                         : (320 + (cs - 4) * 32 + (sc - 32));
}

// ---------------- generic helpers -------------------------------------------
__device__ __forceinline__ float silu_f(float x) {
    return x / (1.0f + __expf(-x));
}
__device__ __forceinline__ float4 f4mul(float4 a, float4 b) {
    return make_float4(a.x * b.x, a.y * b.y, a.z * b.z, a.w * b.w);
}
__device__ __forceinline__ float4 f4scale(float4 a, float s) {
    return make_float4(a.x * s, a.y * s, a.z * s, a.w * s);
}
__device__ __forceinline__ float4 f4fmas(float4 a, float s, float4 c) {
    return make_float4(fmaf(a.x, s, c.x), fmaf(a.y, s, c.y),
                       fmaf(a.z, s, c.z), fmaf(a.w, s, c.w));
}
__device__ __forceinline__ void red4(float* p, float4 v) {
    asm volatile("red.global.add.v4.f32 [%0], {%1, %2, %3, %4};"
                 :: "l"(p), "f"(v.x), "f"(v.y), "f"(v.z), "f"(v.w)
                 : "memory");
}
__device__ __forceinline__ unsigned short bf_bits(__nv_bfloat16 h) {
    return *(unsigned short*)&h;
}
__device__ __forceinline__ void bf_split(float x, unsigned short& hi,
                                         unsigned short& lo) {
    const __nv_bfloat16 h = __float2bfloat16(x);
    const __nv_bfloat16 l = __float2bfloat16(x - __bfloat162float(h));
    hi = bf_bits(h);
    lo = bf_bits(l);
}

// mma.sync m16n8k16 bf16, fp32 accum
__device__ __forceinline__ void mma_bf16(float c[4], const uint4& a,
                                         uint32_t b0, uint32_t b1) {
    asm volatile(
        "mma.sync.aligned.m16n8k16.row.col.f32.bf16.bf16.f32 "
        "{%0,%1,%2,%3}, {%4,%5,%6,%7}, {%8,%9}, {%0,%1,%2,%3};"
        : "+f"(c[0]), "+f"(c[1]), "+f"(c[2]), "+f"(c[3])
        : "r"(a.x), "r"(a.y), "r"(a.z), "r"(a.w), "r"(b0), "r"(b1));
}

// cp.async + mbarrier helpers
__device__ __forceinline__ void cp16(void* dst_smem, const void* src) {
    uint32_t d = (uint32_t)__cvta_generic_to_shared(dst_smem);
    asm volatile("cp.async.cg.shared.global [%0], [%1], 16;"
                 :: "r"(d), "l"(src) : "memory");
}
#define MBAR_INIT(mb, n) \
    asm volatile("mbarrier.init.shared.b64 [%0], %1;" \
                 :: "r"(mb), "r"((uint32_t)(n)) : "memory")
#define MBAR_ARRIVE(mb) \
    asm volatile("mbarrier.arrive.shared.b64 _, [%0];" :: "r"(mb) : "memory")
#define CP_MBAR_ARRIVE(mb) \
    asm volatile("cp.async.mbarrier.arrive.noinc.shared.b64 [%0];" \
                 :: "r"(mb) : "memory")
#define MBAR_TRYWAIT(mb, par) do { \
    asm volatile( \
        "{\n\t.reg .pred P1;\n\t" \
        "WL_%=:\n\t" \
        "mbarrier.try_wait.parity.shared.b64 P1, [%0], %1;\n\t" \
        "@P1 bra.uni WD_%=;\n\t" \
        "bra.uni WL_%=;\n\t" \
        "WD_%=:\n\t}" \
        :: "r"(mb), "r"((uint32_t)(par)) : "memory"); \
} while (0)

// ---------------- K1: node pre-mix ------------------------------------------
__global__ __launch_bounds__(320) void k_node_pre(
    const float* __restrict__ nf, const float* __restrict__ Ws,
    const float* __restrict__ bs, const float* __restrict__ Wv)
{
    __shared__ float sv[8][320];
    const int n0 = blockIdx.x * 8;
    const int tid = threadIdx.x;

    for (int idx = tid; idx < 8 * 320; idx += 320) {
        sv[idx / 320][idx % 320] = nf[(n0 + idx / 320) * 320 + idx % 320];
    }
    __syncthreads();

    if (tid < 128) {
        const int j = tid;
        float acc[8];
#pragma unroll
        for (int i = 0; i < 8; i++) acc[i] = 0.0f;
        for (int u = 0; u < 128; u++) {
            const float w = Ws[u * 128 + j];
#pragma unroll
            for (int i = 0; i < 8; i++) acc[i] = fmaf(sv[i][u], w, acc[i]);
        }
        const float b = bs[j];
#pragma unroll
        for (int i = 0; i < 8; i++)
            g_xs[(n0 + i) * 128 + j] = fmaf(acc[i], INV_SQRT_NS, b);
    } else {
        const int t = tid - 128;
        const int c = t / 64, vp = t % 64;
        float acc[8];
#pragma unroll
        for (int i = 0; i < 8; i++) acc[i] = 0.0f;
        for (int u = 0; u < 64; u++) {
            const float w = Wv[u * 64 + vp];
#pragma unroll
            for (int i = 0; i < 8; i++)
                acc[i] = fmaf(sv[i][128 + 3 * u + c], w, acc[i]);
        }
#pragma unroll
        for (int i = 0; i < 8; i++)
            g_xv[(n0 + i) * 192 + c * 64 + vp] = acc[i] * INV_SQRT_NV;
    }
}

// ---------------- prep: W2 -> packed, PERMUTED B fragments -------------------
__global__ __launch_bounds__(256) void k_prep_b(const float* __restrict__ W2)
{
    const int idx = blockIdx.x * 256 + threadIdx.x;
    if (idx >= 6 * 8 * 8 * 32) return;
    const int lane = idx & 31;
    const int jj = (idx >> 5) & 7;
    const int s = (idx >> 8) & 7;
    const int cs = idx >> 11;

    const int gid = lane >> 2;
    const int tig = lane & 3;
    const int wcol = perm_col(cs, jj * 8 + gid);
    const int k0 = s * 16 + tig * 2;

    unsigned short h0, l0, h1, l1, h2, l2, h3, l3;
    bf_split(W2[k0 * 384 + wcol],       h0, l0);
    bf_split(W2[(k0 + 1) * 384 + wcol], h1, l1);
    bf_split(W2[(k0 + 8) * 384 + wcol], h2, l2);
    bf_split(W2[(k0 + 9) * 384 + wcol], h3, l3);

    uint4 p;
    p.x = (uint32_t)h0 | ((uint32_t)h1 << 16);
    p.y = (uint32_t)h2 | ((uint32_t)h3 << 16);
    p.z = (uint32_t)l0 | ((uint32_t)l1 << 16);
    p.w = (uint32_t)l2 | ((uint32_t)l3 << 16);
    g_Bpk[((cs * 8 + s) * 8 + jj) * 32 + lane] = p;
}

// ---------------- prep: transpose post weights -------------------------------
__global__ __launch_bounds__(256) void k_prep_post(
    const float* __restrict__ Wps, const float* __restrict__ Wpv)
{
    const int idx = blockIdx.x * 256 + threadIdx.x;
    if (idx < 192 * 128) {
        const int u = idx / 128, j = idx % 128;
        g_WpsT[j * 192 + u] = Wps[u * 128 + j];
    }
    if (idx < 192 * 64) {
        const int u = idx / 64, v = idx % 64;
        g_WpvT[v * 192 + u] = Wpv[u * 64 + v];
    }
}

// ---------------- K2: edge MLP layer 1 -> h hi/lo bf16 -----------------------
__global__ __launch_bounds__(256) void k_edge_mlp1(
    const float* __restrict__ ea, const float* __restrict__ W1,
    const float* __restrict__ b1)
{
    __shared__ float W1s[16 * 128];
    __shared__ float b1s[128];
    __shared__ float eas[8][16];
    const int tid = threadIdx.x;
    const int e0 = blockIdx.x * 8;

    for (int idx = tid; idx < 2048; idx += 256) W1s[idx] = W1[idx];
    if (tid < 128) {
        b1s[tid] = b1[tid];
        eas[tid / 16][tid % 16] = ea[e0 * 16 + tid];
    }
    __syncthreads();

    const int i = tid >> 5;
    const int q = (tid & 31) * 4;
    float4 acc = *(const float4*)(b1s + q);
#pragma unroll
    for (int k = 0; k < 16; k++) {
        const float a = eas[i][k];
        const float4 w = *(const float4*)(W1s + k * 128 + q);
        acc = f4fmas(w, a, acc);
    }
    float v[4];
    v[0] = silu_f(acc.x); v[1] = silu_f(acc.y);
    v[2] = silu_f(acc.z); v[3] = silu_f(acc.w);

    unsigned short hb[4], lb[4];
#pragma unroll
    for (int j = 0; j < 4; j++) bf_split(v[j], hb[j], lb[j]);

    const size_t base = (size_t)(e0 + i) * 128 + q;
    uint2 ph, pl;
    ph.x = (uint32_t)hb[0] | ((uint32_t)hb[1] << 16);
    ph.y = (uint32_t)hb[2] | ((uint32_t)hb[3] << 16);
    pl.x = (uint32_t)lb[0] | ((uint32_t)lb[1] << 16);
    pl.y = (uint32_t)lb[2] | ((uint32_t)lb[3] << 16);
    *(uint2*)(g_hhi + base) = ph;
    *(uint2*)(g_hlo + base) = pl;
}

// ---------------- K3: FUSED tensor GEMM + message scatter (mbar pipeline) ----
#define SA_STRIDE 136
#define SMEM_A_IMG (128 * SA_STRIDE * 2)            // 34816 per image
#define SMEM_B_BYTES 32768
#define SMEM_WS_OFF (2 * SMEM_A_IMG)                // 69632
#define WS_STRIDE 68
#define SMEM_BIAS_OFF (SMEM_WS_OFF + 128 * WS_STRIDE * 4)   // 104448
#define SMEM_EIDX_OFF (SMEM_BIAS_OFF + 1536)        // 105984
#define SMEM_R_OFF    (SMEM_EIDX_OFF + 1024)        // 107008
#define SMEM_MB_OFF   (SMEM_R_OFF + 2048)           // 109056
#define SMEM_MMA_BYTES (SMEM_MB_OFF + 64)           // 109120
__global__ __launch_bounds__(256, 2) void k_mlp2_fused(
    const float* __restrict__ b2,
    const int* __restrict__ eidx, const float* __restrict__ rsh)
{
    extern __shared__ unsigned char smem[];
    __nv_bfloat16* sAh = (__nv_bfloat16*)smem;
    __nv_bfloat16* sAl = (__nv_bfloat16*)(smem + SMEM_A_IMG);
    float* ws = (float*)(smem + SMEM_WS_OFF);
    float* sbias = (float*)(smem + SMEM_BIAS_OFF);
    int* sDst = (int*)(smem + SMEM_EIDX_OFF);
    int* sSrc = sDst + 128;
    float4* sR4 = (float4*)(smem + SMEM_R_OFF);
    const uint32_t mbF =
        (uint32_t)__cvta_generic_to_shared(smem + SMEM_MB_OFF);
    const uint32_t mbE = mbF + 16;

    const int tid = threadIdx.x;
    const int warp = tid >> 5;
    const int lane = tid & 31;
    const int tile = blockIdx.x;
    const int gid = lane >> 2;
    const int tig = lane & 3;
    const int row0 = warp * 16 + gid;

    // ---- stage A once; load bias (permuted), edge meta; init mbarriers ----
    {
        const uint2* ghh = (const uint2*)(g_hhi + (size_t)tile * 16384);
        const uint2* ghl = (const uint2*)(g_hlo + (size_t)tile * 16384);
        for (int i = tid; i < 4096; i += 256) {
            const int r = i >> 5, q = (i & 31) * 4;
            *(uint2*)&sAh[r * SA_STRIDE + q] = ghh[i];
            *(uint2*)&sAl[r * SA_STRIDE + q] = ghl[i];
        }
    }
    for (int i = tid; i < 384; i += 256)
        sbias[i] = b2[perm_col(i / 64, i % 64)];
    if (tid < 128) {
        sDst[tid] = eidx[tile * 128 + tid];
        sSrc[tid] = eidx[NEDGES + tile * 128 + tid];
        sR4[tid] = *(const float4*)(rsh + 4 * (tile * 128 + tid));
    }
    if (tid == 0) {
        MBAR_INIT(mbF + 0, 256);
        MBAR_INIT(mbF + 8, 256);
        MBAR_INIT(mbE + 0, 256);
        MBAR_INIT(mbE + 8, 256);
    }
    __syncthreads();

    uint4 ah[8], al[8];
#pragma unroll
    for (int s = 0; s < 8; s++) {
        const int kb = s * 16 + tig * 2;
        ah[s].x = *(const uint32_t*)&sAh[row0 * SA_STRIDE + kb];
        ah[s].y = *(const uint32_t*)&sAh[(row0 + 8) * SA_STRIDE + kb];
        ah[s].z = *(const uint32_t*)&sAh[row0 * SA_STRIDE + kb + 8];
        ah[s].w = *(const uint32_t*)&sAh[(row0 + 8) * SA_STRIDE + kb + 8];
        al[s].x = *(const uint32_t*)&sAl[row0 * SA_STRIDE + kb];
        al[s].y = *(const uint32_t*)&sAl[(row0 + 8) * SA_STRIDE + kb];
        al[s].z = *(const uint32_t*)&sAl[row0 * SA_STRIDE + kb + 8];
        al[s].w = *(const uint32_t*)&sAl[(row0 + 8) * SA_STRIDE + kb + 8];
    }
    __syncthreads();     // A region released -> reused as B double buffer

    // prefetch stage 0 into buf0
    {
        const uint4* srcp = g_Bpk;
        uint4* dstp = (uint4*)smem;
#pragma unroll
        for (int i = 0; i < 8; i++)
            cp16(&dstp[tid + i * 256], &srcp[tid + i * 256]);
        CP_MBAR_ARRIVE(mbF + 0);
    }

    const int half16 = lane >> 4;        // edge of pair
    const int sub = lane & 15;
    const int typ = sub >> 3;            // 0: ss/vv, 1: sv/vs
    const int l4 = (sub & 7) * 4;        // col group within 32

    for (int cs = 0; cs < 6; cs++) {
        if (cs < 5) {
            const int b = (cs + 1) & 1;
            if (cs >= 1) MBAR_TRYWAIT(mbE + b * 8, ((cs - 1) >> 1) & 1);
            const uint4* srcp = g_Bpk + (cs + 1) * 2048;
            uint4* dstp = (uint4*)(smem + b * SMEM_B_BYTES);
#pragma unroll
            for (int i = 0; i < 8; i++)
                cp16(&dstp[tid + i * 256], &srcp[tid + i * 256]);
            CP_MBAR_ARRIVE(mbF + b * 8);
        }
        const int bc = cs & 1;
        MBAR_TRYWAIT(mbF + bc * 8, (cs >> 1) & 1);
        const uint4* bb = (const uint4*)(smem + bc * SMEM_B_BYTES);

        float c[8][4];
#pragma unroll
        for (int j = 0; j < 8; j++)
#pragma unroll
            for (int q = 0; q < 4; q++) c[j][q] = 0.0f;

#pragma unroll
        for (int s = 0; s < 8; s++) {
#pragma unroll
            for (int j = 0; j < 8; j++) {
                const uint4 b = bb[(s * 8 + j) * 32 + lane];
                mma_bf16(c[j], ah[s], b.x, b.y);
                mma_bf16(c[j], ah[s], b.z, b.w);
                mma_bf16(c[j], al[s], b.x, b.y);
            }
        }
        MBAR_ARRIVE(mbE + bc * 8);   // done reading this B buffer

        // ---- stage w to warp-local ws rows (bias added) ----
        const int cbase = cs * 64;
#pragma unroll
        for (int j = 0; j < 8; j++) {
            const int cl = j * 8 + tig * 2;
            const float bx = sbias[cbase + cl], by = sbias[cbase + cl + 1];
            *(float2*)&ws[row0 * WS_STRIDE + cl] =
                make_float2(c[j][0] + bx, c[j][1] + by);
            *(float2*)&ws[(row0 + 8) * WS_STRIDE + cl] =
                make_float2(c[j][2] + bx, c[j][3] + by);
        }
        __syncwarp();

        // ---- scatter: 2 edges per iter, 16 lanes each (typ splits cols) ----
#pragma unroll
        for (int it = 0; it < 8; it++) {
            const int t = warp * 16 + it * 2 + half16;
            const int dst = sDst[t];
            const int src = sSrc[t];
            const float4 r = sR4[t];
            const float4 w = *(const float4*)&ws[t * WS_STRIDE + typ * 32 + l4];
            float* as_ = g_accs + dst * 192;
            float* av = g_accv + dst * 576;

            if (cs < 4) {
                const int scol = cs * 32 + l4;
                const float4 sj = *(const float4*)(g_xs + src * 128 + scol);
                if (typ == 0) {
                    red4(as_ + scol, f4scale(f4mul(w, sj), r.x));
                } else {
                    const float4 base = f4mul(w, sj);
                    red4(av + scol,       f4scale(base, r.y));
                    red4(av + 192 + scol, f4scale(base, r.z));
                    red4(av + 384 + scol, f4scale(base, r.w));
                }
            } else {
                const int u = (cs - 4) * 32 + l4;
                const float* xv = g_xv + src * 192;
                const float4 v0 = *(const float4*)(xv + u);
                const float4 v1 = *(const float4*)(xv + 64 + u);
                const float4 v2 = *(const float4*)(xv + 128 + u);
                if (typ == 0) {
                    float4 vd = f4scale(v0, r.y);
                    vd = f4fmas(v1, r.z, vd);
                    vd = f4fmas(v2, r.w, vd);
                    red4(as_ + 128 + u, f4scale(f4mul(w, vd), INV_SQRT3));
                } else {
                    const float4 wr = f4scale(w, r.x);
                    red4(av + 128 + u, f4mul(wr, v0));
                    red4(av + 320 + u, f4mul(wr, v1));
                    red4(av + 512 + u, f4mul(wr, v2));
                }
            }
        }
    }
}

// ---------------- K5: gating + node post-mix (transposed W) ------------------
__global__ __launch_bounds__(320) void k_node_post(
    float* __restrict__ out)
{
    __shared__ float gs[8][192];
    __shared__ float gv[8][3][192];
    const int n0 = blockIdx.x * 8;
    const int tid = threadIdx.x;

    for (int idx = tid; idx < 8 * 192; idx += 320) {
        const int i = idx / 192, u = idx % 192;
        const float a = g_accs[(n0 + i) * 192 + u];
        gs[i][u] = silu_f(a);
        const float v0 = g_accv[(n0 + i) * 576 + u];
        const float v1 = g_accv[(n0 + i) * 576 + 192 + u];
        const float v2 = g_accv[(n0 + i) * 576 + 384 + u];
        const float nrm = sqrtf(fmaf(v0, v0, fmaf(v1, v1, fmaf(v2, v2, 1e-12f))));
        const float sg = 1.0f / (1.0f + __expf(-nrm));
        gv[i][0][u] = v0 * sg;
        gv[i][1][u] = v1 * sg;
        gv[i][2][u] = v2 * sg;
    }
    __syncthreads();

    if (tid < 128) {
        const int j = tid;
        const float4* wrow = (const float4*)(g_WpsT + j * 192);
        float acc[8];
#pragma unroll
        for (int i = 0; i < 8; i++) acc[i] = 0.0f;
        for (int u = 0; u < 192; u += 4) {
            const float4 w = wrow[u >> 2];
#pragma unroll
            for (int i = 0; i < 8; i++) {
                const float4 g = *(const float4*)&gs[i][u];
                acc[i] = fmaf(g.x, w.x, acc[i]);
                acc[i] = fmaf(g.y, w.y, acc[i]);
                acc[i] = fmaf(g.z, w.z, acc[i]);
                acc[i] = fmaf(g.w, w.w, acc[i]);
            }
        }
#pragma unroll
        for (int i = 0; i < 8; i++)
            out[(n0 + i) * 320 + j] =
                g_xs[(n0 + i) * 128 + j] + acc[i] * INV_SQRT_TPC;
    } else {
        const int t = tid - 128;
        const int c = t / 64, vp = t % 64;
        const float4* wrow = (const float4*)(g_WpvT + vp * 192);
        float acc[8];
#pragma unroll
        for (int i = 0; i < 8; i++) acc[i] = 0.0f;
        for (int u = 0; u < 192; u += 4) {
            const float4 w = wrow[u >> 2];
#pragma unroll
            for (int i = 0; i < 8; i++) {
                const float4 g = *(const float4*)&gv[i][c][u];
                acc[i] = fmaf(g.x, w.x, acc[i]);
                acc[i] = fmaf(g.y, w.y, acc[i]);
                acc[i] = fmaf(g.z, w.z, acc[i]);
                acc[i] = fmaf(g.w, w.w, acc[i]);
            }
        }
#pragma unroll
        for (int i = 0; i < 8; i++)
            out[(n0 + i) * 320 + 128 + vp * 3 + c] =
                g_xv[(n0 + i) * 192 + c * 64 + vp] + acc[i] * INV_SQRT_TPC;
    }
}

// ---------------- launcher ---------------------------------------------------
extern "C" void kernel_launch(void* const* d_in, const int* in_sizes, int n_in,
                              void* d_out, int out_size)
{
    (void)in_sizes; (void)n_in; (void)out_size;
    const float* nf   = (const float*)d_in[0];
    const float* ea   = (const float*)d_in[1];
    const float* rsh  = (const float*)d_in[2];
    const int*   eidx = (const int*)d_in[3];
    const float* Wps  = (const float*)d_in[4];
    const float* bps  = (const float*)d_in[5];
    const float* Wpv  = (const float*)d_in[6];
    const float* W1   = (const float*)d_in[7];
    const float* b1   = (const float*)d_in[8];
    const float* W2   = (const float*)d_in[9];
    const float* b2   = (const float*)d_in[10];
    const float* Wposts = (const float*)d_in[11];
    const float* Wpostv = (const float*)d_in[12];
    float* out = (float*)d_out;

    cudaFuncSetAttribute(k_mlp2_fused,
                         cudaFuncAttributeMaxDynamicSharedMemorySize,
                         SMEM_MMA_BYTES);

    void* accs_ptr = nullptr;
    void* accv_ptr = nullptr;
    cudaGetSymbolAddress(&accs_ptr, g_accs);
    cudaGetSymbolAddress(&accv_ptr, g_accv);
    cudaMemsetAsync(accs_ptr, 0, sizeof(float) * NNODES * TPCC);
    cudaMemsetAsync(accv_ptr, 0, sizeof(float) * NNODES * 3 * TPCC);

    k_node_pre<<<NNODES / 8, 320>>>(nf, Wps, bps, Wpv);
    k_prep_b<<<48, 256>>>(W2);
    k_prep_post<<<96, 256>>>(Wposts, Wpostv);
    k_edge_mlp1<<<NEDGES / 8, 256>>>(ea, W1, b1);
    k_mlp2_fused<<<NTILES, 256, SMEM_MMA_BYTES>>>(b2, eidx, rsh);
    k_node_post<<<NNODES / 8, 320>>>(out);
}

// round 17
// speedup vs baseline: 1.1200x; 1.0836x over previous
#include <cuda_runtime.h>
#include <cuda_bf16.h>
#include <math.h>
#include <stdint.h>

#define NSC 128
#define NVC 64
#define TPCC 192
#define NNODES 16000
#define NEDGES 256000
#define NTILES 2000           // NEDGES / 128

#define INV_SQRT_NS 0.08838834764831845f
#define INV_SQRT_NV 0.125f
#define INV_SQRT_TPC 0.07216878364870323f
#define INV_SQRT3 0.5773502691896258f

// ---------------- scratch (static device globals; no runtime allocs) --------
__device__ float g_xs[NNODES * NSC];            // [n][128]
__device__ float g_xv[NNODES * 3 * NVC];        // [n][c][64]
__device__ float g_accs[NNODES * TPCC];         // [n][192]
__device__ float g_accv[NNODES * 3 * TPCC];     // [n][c][192]
// h split into bf16 hi/lo, row-major [e][128]
__device__ __nv_bfloat16 g_hhi[(size_t)NEDGES * 128];
__device__ __nv_bfloat16 g_hlo[(size_t)NEDGES * 128];
// W2 packed into mma.sync B fragments, PERMUTED stage-major
__device__ uint4 g_Bpk[6 * 8 * 8 * 32];

// stage column permutation: stage cs, within-stage col sc (0..63) -> W2 col.
// S0-3: [ w_ss0[cs*32 : +32] | w_sv1[cs*32 : +32] ]   (share xs gather)
// S4-5: [ w_vv0[(cs-4)*32:+32] | w_vs1[(cs-4)*32:+32] ] (share xv gather)
__host__ __device__ __forceinline__ int perm_col(int cs, int sc) {
    if (cs < 4)
        return (sc < 32) ? (cs * 32 + sc) : (192 + cs * 32 + (sc - 32));
    else
        return (sc < 32) ? (128 + (cs - 4) * 32 + sc)
                         : (320 + (cs - 4) * 32 + (sc - 32));
}

// ---------------- generic helpers -------------------------------------------
__device__ __forceinline__ float silu_f(float x) {
    return x / (1.0f + __expf(-x));
}
__device__ __forceinline__ float4 f4mul(float4 a, float4 b) {
    return make_float4(a.x * b.x, a.y * b.y, a.z * b.z, a.w * b.w);
}
__device__ __forceinline__ float4 f4scale(float4 a, float s) {
    return make_float4(a.x * s, a.y * s, a.z * s, a.w * s);
}
__device__ __forceinline__ float4 f4fmas(float4 a, float s, float4 c) {
    return make_float4(fmaf(a.x, s, c.x), fmaf(a.y, s, c.y),
                       fmaf(a.z, s, c.z), fmaf(a.w, s, c.w));
}
__device__ __forceinline__ void red4(float* p, float4 v) {
    asm volatile("red.global.add.v4.f32 [%0], {%1, %2, %3, %4};"
                 :: "l"(p), "f"(v.x), "f"(v.y), "f"(v.z), "f"(v.w)
                 : "memory");
}
__device__ __forceinline__ unsigned short bf_bits(__nv_bfloat16 h) {
    return *(unsigned short*)&h;
}
__device__ __forceinline__ void bf_split(float x, unsigned short& hi,
                                         unsigned short& lo) {
    const __nv_bfloat16 h = __float2bfloat16(x);
    const __nv_bfloat16 l = __float2bfloat16(x - __bfloat162float(h));
    hi = bf_bits(h);
    lo = bf_bits(l);
}
// pack two floats' bf16(hi) into one u32: {hi(v1)<<16 | hi(v0)}
__device__ __forceinline__ uint32_t bf16x2_pack(float v0, float v1) {
    uint32_t r;
    asm("cvt.rn.bf16x2.f32 %0, %1, %2;" : "=r"(r) : "f"(v1), "f"(v0));
    return r;
}

// mma.sync m16n8k16 bf16, fp32 accum
__device__ __forceinline__ void mma_bf16(float c[4], const uint4& a,
                                         uint32_t b0, uint32_t b1) {
    asm volatile(
        "mma.sync.aligned.m16n8k16.row.col.f32.bf16.bf16.f32 "
        "{%0,%1,%2,%3}, {%4,%5,%6,%7}, {%8,%9}, {%0,%1,%2,%3};"
        : "+f"(c[0]), "+f"(c[1]), "+f"(c[2]), "+f"(c[3])
        : "r"(a.x), "r"(a.y), "r"(a.z), "r"(a.w), "r"(b0), "r"(b1));
}

// cp.async + mbarrier helpers
__device__ __forceinline__ void cp16(void* dst_smem, const void* src) {
    uint32_t d = (uint32_t)__cvta_generic_to_shared(dst_smem);
    asm volatile("cp.async.cg.shared.global [%0], [%1], 16;"
                 :: "r"(d), "l"(src) : "memory");
}
#define MBAR_INIT(mb, n) \
    asm volatile("mbarrier.init.shared.b64 [%0], %1;" \
                 :: "r"(mb), "r"((uint32_t)(n)) : "memory")
#define MBAR_ARRIVE(mb) \
    asm volatile("mbarrier.arrive.shared.b64 _, [%0];" :: "r"(mb) : "memory")
#define CP_MBAR_ARRIVE(mb) \
    asm volatile("cp.async.mbarrier.arrive.noinc.shared.b64 [%0];" \
                 :: "r"(mb) : "memory")
#define MBAR_TRYWAIT(mb, par) do { \
    asm volatile( \
        "{\n\t.reg .pred P1;\n\t" \
        "WL_%=:\n\t" \
        "mbarrier.try_wait.parity.shared.b64 P1, [%0], %1;\n\t" \
        "@P1 bra.uni WD_%=;\n\t" \
        "bra.uni WL_%=;\n\t" \
        "WD_%=:\n\t}" \
        :: "r"(mb), "r"((uint32_t)(par)) : "memory"); \
} while (0)

// ---------------- K1: node pre-mix ------------------------------------------
__global__ __launch_bounds__(320) void k_node_pre(
    const float* __restrict__ nf, const float* __restrict__ Ws,
    const float* __restrict__ bs, const float* __restrict__ Wv)
{
    __shared__ float sv[8][320];
    const int n0 = blockIdx.x * 8;
    const int tid = threadIdx.x;

    for (int idx = tid; idx < 8 * 320; idx += 320) {
        sv[idx / 320][idx % 320] = nf[(n0 + idx / 320) * 320 + idx % 320];
    }
    __syncthreads();

    if (tid < 128) {
        const int j = tid;
        float acc[8];
#pragma unroll
        for (int i = 0; i < 8; i++) acc[i] = 0.0f;
        for (int u = 0; u < 128; u++) {
            const float w = Ws[u * 128 + j];
#pragma unroll
            for (int i = 0; i < 8; i++) acc[i] = fmaf(sv[i][u], w, acc[i]);
        }
        const float b = bs[j];
#pragma unroll
        for (int i = 0; i < 8; i++)
            g_xs[(n0 + i) * 128 + j] = fmaf(acc[i], INV_SQRT_NS, b);
    } else {
        const int t = tid - 128;
        const int c = t / 64, vp = t % 64;
        float acc[8];
#pragma unroll
        for (int i = 0; i < 8; i++) acc[i] = 0.0f;
        for (int u = 0; u < 64; u++) {
            const float w = Wv[u * 64 + vp];
#pragma unroll
            for (int i = 0; i < 8; i++)
                acc[i] = fmaf(sv[i][128 + 3 * u + c], w, acc[i]);
        }
#pragma unroll
        for (int i = 0; i < 8; i++)
            g_xv[(n0 + i) * 192 + c * 64 + vp] = acc[i] * INV_SQRT_NV;
    }
}

// ---------------- prep: W2 -> packed, PERMUTED B fragments -------------------
__global__ __launch_bounds__(256) void k_prep_b(const float* __restrict__ W2)
{
    const int idx = blockIdx.x * 256 + threadIdx.x;
    if (idx >= 6 * 8 * 8 * 32) return;
    const int lane = idx & 31;
    const int jj = (idx >> 5) & 7;
    const int s = (idx >> 8) & 7;
    const int cs = idx >> 11;

    const int gid = lane >> 2;
    const int tig = lane & 3;
    const int wcol = perm_col(cs, jj * 8 + gid);
    const int k0 = s * 16 + tig * 2;

    unsigned short h0, l0, h1, l1, h2, l2, h3, l3;
    bf_split(W2[k0 * 384 + wcol],       h0, l0);
    bf_split(W2[(k0 + 1) * 384 + wcol], h1, l1);
    bf_split(W2[(k0 + 8) * 384 + wcol], h2, l2);
    bf_split(W2[(k0 + 9) * 384 + wcol], h3, l3);

    uint4 p;
    p.x = (uint32_t)h0 | ((uint32_t)h1 << 16);
    p.y = (uint32_t)h2 | ((uint32_t)h3 << 16);
    p.z = (uint32_t)l0 | ((uint32_t)l1 << 16);
    p.w = (uint32_t)l2 | ((uint32_t)l3 << 16);
    g_Bpk[((cs * 8 + s) * 8 + jj) * 32 + lane] = p;
}

// ---------------- K2: edge MLP layer 1 -> h hi/lo bf16 (bf16x2 packing) ------
__global__ __launch_bounds__(256) void k_edge_mlp1(
    const float* __restrict__ ea, const float* __restrict__ W1,
    const float* __restrict__ b1)
{
    __shared__ float W1s[16 * 128];
    __shared__ float b1s[128];
    __shared__ float eas[8][16];
    const int tid = threadIdx.x;
    const int e0 = blockIdx.x * 8;

    for (int idx = tid; idx < 2048; idx += 256) W1s[idx] = W1[idx];
    if (tid < 128) {
        b1s[tid] = b1[tid];
        eas[tid / 16][tid % 16] = ea[e0 * 16 + tid];
    }
    __syncthreads();

    const int i = tid >> 5;
    const int q = (tid & 31) * 4;
    float4 acc = *(const float4*)(b1s + q);
#pragma unroll
    for (int k = 0; k < 16; k++) {
        const float a = eas[i][k];
        const float4 w = *(const float4*)(W1s + k * 128 + q);
        acc = f4fmas(w, a, acc);
    }
    const float v0 = silu_f(acc.x), v1 = silu_f(acc.y);
    const float v2 = silu_f(acc.z), v3 = silu_f(acc.w);

    // hi pairs via single-instruction bf16x2 converts
    const uint32_t ph0 = bf16x2_pack(v0, v1);
    const uint32_t ph1 = bf16x2_pack(v2, v3);
    // recover hi as floats from the packed bits (bf16 -> f32 is a shift)
    const float h0f = __uint_as_float(ph0 << 16);
    const float h1f = __uint_as_float(ph0 & 0xFFFF0000u);
    const float h2f = __uint_as_float(ph1 << 16);
    const float h3f = __uint_as_float(ph1 & 0xFFFF0000u);
    const uint32_t pl0 = bf16x2_pack(v0 - h0f, v1 - h1f);
    const uint32_t pl1 = bf16x2_pack(v2 - h2f, v3 - h3f);

    const size_t base = (size_t)(e0 + i) * 128 + q;
    *(uint2*)(g_hhi + base) = make_uint2(ph0, ph1);
    *(uint2*)(g_hlo + base) = make_uint2(pl0, pl1);
}

// ---------------- K3: FUSED tensor GEMM + message scatter (mbar pipeline) ----
#define SA_STRIDE 136
#define SMEM_A_IMG (128 * SA_STRIDE * 2)            // 34816 per image
#define SMEM_B_BYTES 32768
#define SMEM_WS_OFF (2 * SMEM_A_IMG)                // 69632
#define WS_STRIDE 68
#define SMEM_BIAS_OFF (SMEM_WS_OFF + 128 * WS_STRIDE * 4)   // 104448
#define SMEM_EIDX_OFF (SMEM_BIAS_OFF + 1536)        // 105984
#define SMEM_R_OFF    (SMEM_EIDX_OFF + 1024)        // 107008
#define SMEM_MB_OFF   (SMEM_R_OFF + 2048)           // 109056
#define SMEM_MMA_BYTES (SMEM_MB_OFF + 64)           // 109120
__global__ __launch_bounds__(256, 2) void k_mlp2_fused(
    const float* __restrict__ b2,
    const int* __restrict__ eidx, const float* __restrict__ rsh)
{
    extern __shared__ unsigned char smem[];
    __nv_bfloat16* sAh = (__nv_bfloat16*)smem;
    __nv_bfloat16* sAl = (__nv_bfloat16*)(smem + SMEM_A_IMG);
    float* ws = (float*)(smem + SMEM_WS_OFF);
    float* sbias = (float*)(smem + SMEM_BIAS_OFF);
    int* sDst = (int*)(smem + SMEM_EIDX_OFF);
    int* sSrc = sDst + 128;
    float4* sR4 = (float4*)(smem + SMEM_R_OFF);
    const uint32_t mbF =
        (uint32_t)__cvta_generic_to_shared(smem + SMEM_MB_OFF);
    const uint32_t mbE = mbF + 16;

    const int tid = threadIdx.x;
    const int warp = tid >> 5;
    const int lane = tid & 31;
    const int tile = blockIdx.x;
    const int gid = lane >> 2;
    const int tig = lane & 3;
    const int row0 = warp * 16 + gid;

    // ---- stage A once; load bias (permuted), edge meta; init mbarriers ----
    {
        const uint2* ghh = (const uint2*)(g_hhi + (size_t)tile * 16384);
        const uint2* ghl = (const uint2*)(g_hlo + (size_t)tile * 16384);
        for (int i = tid; i < 4096; i += 256) {
            const int r = i >> 5, q = (i & 31) * 4;
            *(uint2*)&sAh[r * SA_STRIDE + q] = ghh[i];
            *(uint2*)&sAl[r * SA_STRIDE + q] = ghl[i];
        }
    }
    for (int i = tid; i < 384; i += 256)
        sbias[i] = b2[perm_col(i / 64, i % 64)];
    if (tid < 128) {
        sDst[tid] = eidx[tile * 128 + tid];
        sSrc[tid] = eidx[NEDGES + tile * 128 + tid];
        sR4[tid] = *(const float4*)(rsh + 4 * (tile * 128 + tid));
    }
    if (tid == 0) {
        MBAR_INIT(mbF + 0, 256);
        MBAR_INIT(mbF + 8, 256);
        MBAR_INIT(mbE + 0, 256);
        MBAR_INIT(mbE + 8, 256);
    }
    __syncthreads();

    uint4 ah[8], al[8];
#pragma unroll
    for (int s = 0; s < 8; s++) {
        const int kb = s * 16 + tig * 2;
        ah[s].x = *(const uint32_t*)&sAh[row0 * SA_STRIDE + kb];
        ah[s].y = *(const uint32_t*)&sAh[(row0 + 8) * SA_STRIDE + kb];
        ah[s].z = *(const uint32_t*)&sAh[row0 * SA_STRIDE + kb + 8];
        ah[s].w = *(const uint32_t*)&sAh[(row0 + 8) * SA_STRIDE + kb + 8];
        al[s].x = *(const uint32_t*)&sAl[row0 * SA_STRIDE + kb];
        al[s].y = *(const uint32_t*)&sAl[(row0 + 8) * SA_STRIDE + kb];
        al[s].z = *(const uint32_t*)&sAl[row0 * SA_STRIDE + kb + 8];
        al[s].w = *(const uint32_t*)&sAl[(row0 + 8) * SA_STRIDE + kb + 8];
    }
    __syncthreads();     // A region released -> reused as B double buffer

    // prefetch stage 0 into buf0
    {
        const uint4* srcp = g_Bpk;
        uint4* dstp = (uint4*)smem;
#pragma unroll
        for (int i = 0; i < 8; i++)
            cp16(&dstp[tid + i * 256], &srcp[tid + i * 256]);
        CP_MBAR_ARRIVE(mbF + 0);
    }

    const int half16 = lane >> 4;        // edge of pair
    const int sub = lane & 15;
    const int typ = sub >> 3;            // 0: ss/vv, 1: sv/vs
    const int l4 = (sub & 7) * 4;        // col group within 32

    for (int cs = 0; cs < 6; cs++) {
        if (cs < 5) {
            const int b = (cs + 1) & 1;
            if (cs >= 1) MBAR_TRYWAIT(mbE + b * 8, ((cs - 1) >> 1) & 1);
            const uint4* srcp = g_Bpk + (cs + 1) * 2048;
            uint4* dstp = (uint4*)(smem + b * SMEM_B_BYTES);
#pragma unroll
            for (int i = 0; i < 8; i++)
                cp16(&dstp[tid + i * 256], &srcp[tid + i * 256]);
            CP_MBAR_ARRIVE(mbF + b * 8);
        }
        const int bc = cs & 1;
        MBAR_TRYWAIT(mbF + bc * 8, (cs >> 1) & 1);
        const uint4* bb = (const uint4*)(smem + bc * SMEM_B_BYTES);

        float c[8][4];
#pragma unroll
        for (int j = 0; j < 8; j++)
#pragma unroll
            for (int q = 0; q < 4; q++) c[j][q] = 0.0f;

#pragma unroll
        for (int s = 0; s < 8; s++) {
#pragma unroll
            for (int j = 0; j < 8; j++) {
                const uint4 b = bb[(s * 8 + j) * 32 + lane];
                mma_bf16(c[j], ah[s], b.x, b.y);
                mma_bf16(c[j], ah[s], b.z, b.w);
                mma_bf16(c[j], al[s], b.x, b.y);
            }
        }
        MBAR_ARRIVE(mbE + bc * 8);   // done reading this B buffer

        // ---- stage w to warp-local ws rows (bias added) ----
        const int cbase = cs * 64;
#pragma unroll
        for (int j = 0; j < 8; j++) {
            const int cl = j * 8 + tig * 2;
            const float bx = sbias[cbase + cl], by = sbias[cbase + cl + 1];
            *(float2*)&ws[row0 * WS_STRIDE + cl] =
                make_float2(c[j][0] + bx, c[j][1] + by);
            *(float2*)&ws[(row0 + 8) * WS_STRIDE + cl] =
                make_float2(c[j][2] + bx, c[j][3] + by);
        }
        __syncwarp();

        // ---- scatter: 2 edges per iter, 16 lanes each (typ splits cols) ----
#pragma unroll
        for (int it = 0; it < 8; it++) {
            const int t = warp * 16 + it * 2 + half16;
            const int dst = sDst[t];
            const int src = sSrc[t];
            const float4 r = sR4[t];
            const float4 w = *(const float4*)&ws[t * WS_STRIDE + typ * 32 + l4];
            float* as_ = g_accs + dst * 192;
            float* av = g_accv + dst * 576;

            if (cs < 4) {
                const int scol = cs * 32 + l4;
                const float4 sj = *(const float4*)(g_xs + src * 128 + scol);
                if (typ == 0) {
                    red4(as_ + scol, f4scale(f4mul(w, sj), r.x));
                } else {
                    const float4 base = f4mul(w, sj);
                    red4(av + scol,       f4scale(base, r.y));
                    red4(av + 192 + scol, f4scale(base, r.z));
                    red4(av + 384 + scol, f4scale(base, r.w));
                }
            } else {
                const int u = (cs - 4) * 32 + l4;
                const float* xv = g_xv + src * 192;
                const float4 v0 = *(const float4*)(xv + u);
                const float4 v1 = *(const float4*)(xv + 64 + u);
                const float4 v2 = *(const float4*)(xv + 128 + u);
                if (typ == 0) {
                    float4 vd = f4scale(v0, r.y);
                    vd = f4fmas(v1, r.z, vd);
                    vd = f4fmas(v2, r.w, vd);
                    red4(as_ + 128 + u, f4scale(f4mul(w, vd), INV_SQRT3));
                } else {
                    const float4 wr = f4scale(w, r.x);
                    red4(av + 128 + u, f4mul(wr, v0));
                    red4(av + 320 + u, f4mul(wr, v1));
                    red4(av + 512 + u, f4mul(wr, v2));
                }
            }
        }
    }
}

// ---------------- K5: gating + node post-mix + residual (R13 version) --------
__global__ __launch_bounds__(320) void k_node_post(
    const float* __restrict__ Wps, const float* __restrict__ Wpv,
    float* __restrict__ out)
{
    __shared__ float gs[8][192];
    __shared__ float gv[8][3][192];
    const int n0 = blockIdx.x * 8;
    const int tid = threadIdx.x;

    for (int idx = tid; idx < 8 * 192; idx += 320) {
        const int i = idx / 192, u = idx % 192;
        const float a = g_accs[(n0 + i) * 192 + u];
        gs[i][u] = silu_f(a);
        const float v0 = g_accv[(n0 + i) * 576 + u];
        const float v1 = g_accv[(n0 + i) * 576 + 192 + u];
        const float v2 = g_accv[(n0 + i) * 576 + 384 + u];
        const float nrm = sqrtf(fmaf(v0, v0, fmaf(v1, v1, fmaf(v2, v2, 1e-12f))));
        const float sg = 1.0f / (1.0f + __expf(-nrm));
        gv[i][0][u] = v0 * sg;
        gv[i][1][u] = v1 * sg;
        gv[i][2][u] = v2 * sg;
    }
    __syncthreads();

    if (tid < 128) {
        const int j = tid;
        float acc[8];
#pragma unroll
        for (int i = 0; i < 8; i++) acc[i] = 0.0f;
        for (int u = 0; u < 192; u += 4) {
            float4 w;
            w.x = Wps[u * 128 + j];
            w.y = Wps[(u + 1) * 128 + j];
            w.z = Wps[(u + 2) * 128 + j];
            w.w = Wps[(u + 3) * 128 + j];
#pragma unroll
            for (int i = 0; i < 8; i++) {
                const float4 g = *(const float4*)&gs[i][u];
                acc[i] = fmaf(g.x, w.x, acc[i]);
                acc[i] = fmaf(g.y, w.y, acc[i]);
                acc[i] = fmaf(g.z, w.z, acc[i]);
                acc[i] = fmaf(g.w, w.w, acc[i]);
            }
        }
#pragma unroll
        for (int i = 0; i < 8; i++)
            out[(n0 + i) * 320 + j] =
                g_xs[(n0 + i) * 128 + j] + acc[i] * INV_SQRT_TPC;
    } else {
        const int t = tid - 128;
        const int c = t / 64, vp = t % 64;
        float acc[8];
#pragma unroll
        for (int i = 0; i < 8; i++) acc[i] = 0.0f;
        for (int u = 0; u < 192; u += 4) {
            float4 w;
            w.x = Wpv[u * 64 + vp];
            w.y = Wpv[(u + 1) * 64 + vp];
            w.z = Wpv[(u + 2) * 64 + vp];
            w.w = Wpv[(u + 3) * 64 + vp];
#pragma unroll
            for (int i = 0; i < 8; i++) {
                const float4 g = *(const float4*)&gv[i][c][u];
                acc[i] = fmaf(g.x, w.x, acc[i]);
                acc[i] = fmaf(g.y, w.y, acc[i]);
                acc[i] = fmaf(g.z, w.z, acc[i]);
                acc[i] = fmaf(g.w, w.w, acc[i]);
            }
        }
#pragma unroll
        for (int i = 0; i < 8; i++)
            out[(n0 + i) * 320 + 128 + vp * 3 + c] =
                g_xv[(n0 + i) * 192 + c * 64 + vp] + acc[i] * INV_SQRT_TPC;
    }
}

// ---------------- launcher ---------------------------------------------------
extern "C" void kernel_launch(void* const* d_in, const int* in_sizes, int n_in,
                              void* d_out, int out_size)
{
    (void)in_sizes; (void)n_in; (void)out_size;
    const float* nf   = (const float*)d_in[0];
    const float* ea   = (const float*)d_in[1];
    const float* rsh  = (const float*)d_in[2];
    const int*   eidx = (const int*)d_in[3];
    const float* Wps  = (const float*)d_in[4];
    const float* bps  = (const float*)d_in[5];
    const float* Wpv  = (const float*)d_in[6];
    const float* W1   = (const float*)d_in[7];
    const float* b1   = (const float*)d_in[8];
    const float* W2   = (const float*)d_in[9];
    const float* b2   = (const float*)d_in[10];
    const float* Wposts = (const float*)d_in[11];
    const float* Wpostv = (const float*)d_in[12];
    float* out = (float*)d_out;

    cudaFuncSetAttribute(k_mlp2_fused,
                         cudaFuncAttributeMaxDynamicSharedMemorySize,
                         SMEM_MMA_BYTES);

    void* accs_ptr = nullptr;
    void* accv_ptr = nullptr;
    cudaGetSymbolAddress(&accs_ptr, g_accs);
    cudaGetSymbolAddress(&accv_ptr, g_accv);
    cudaMemsetAsync(accs_ptr, 0, sizeof(float) * NNODES * TPCC);
    cudaMemsetAsync(accv_ptr, 0, sizeof(float) * NNODES * 3 * TPCC);

    k_node_pre<<<NNODES / 8, 320>>>(nf, Wps, bps, Wpv);
    k_prep_b<<<48, 256>>>(W2);
    k_edge_mlp1<<<NEDGES / 8, 256>>>(ea, W1, b1);
    k_mlp2_fused<<<NTILES, 256, SMEM_MMA_BYTES>>>(b2, eidx, rsh);
    k_node_post<<<NNODES / 8, 320>>>(Wposts, Wpostv, out);
}